// round 5
// baseline (speedup 1.0000x reference)
#include <cuda_runtime.h>
#include <cuda_bf16.h>
#include <math_constants.h>
#include <cstdint>

#define BATCH 2
#define SEQ   2048
#define EMBED 1024
#define HEADS 16
#define HDIM  64
#define MROWS (BATCH * SEQ)   // 4096

// Scratch (alloc-free rule: __device__ globals)
__device__ float g_qkv[(size_t)MROWS * 3 * EMBED];   // [B*N, 3E]
__device__ float g_attn[(size_t)MROWS * EMBED];      // [B*N, E]

// ---------------------------------------------------------------------------
// helpers
// ---------------------------------------------------------------------------
static __device__ __forceinline__ uint32_t smem_u32(const void* p) {
    return (uint32_t)__cvta_generic_to_shared(p);
}

static __device__ __forceinline__ void ldsm4(uint32_t& r0, uint32_t& r1,
                                             uint32_t& r2, uint32_t& r3,
                                             uint32_t addr) {
    asm volatile("ldmatrix.sync.aligned.m8n8.x4.shared.b16 {%0,%1,%2,%3},[%4];\n"
                 : "=r"(r0), "=r"(r1), "=r"(r2), "=r"(r3) : "r"(addr));
}

static __device__ __forceinline__ void ldsm4t(uint32_t& r0, uint32_t& r1,
                                              uint32_t& r2, uint32_t& r3,
                                              uint32_t addr) {
    asm volatile("ldmatrix.sync.aligned.m8n8.x4.trans.shared.b16 {%0,%1,%2,%3},[%4];\n"
                 : "=r"(r0), "=r"(r1), "=r"(r2), "=r"(r3) : "r"(addr));
}

static __device__ __forceinline__ void mma16816(float c[4],
                                                uint32_t a0, uint32_t a1,
                                                uint32_t a2, uint32_t a3,
                                                uint32_t b0, uint32_t b1) {
    asm volatile(
        "mma.sync.aligned.m16n8k16.row.col.f32.bf16.bf16.f32 "
        "{%0,%1,%2,%3},{%4,%5,%6,%7},{%8,%9},{%0,%1,%2,%3};\n"
        : "+f"(c[0]), "+f"(c[1]), "+f"(c[2]), "+f"(c[3])
        : "r"(a0), "r"(a1), "r"(a2), "r"(a3), "r"(b0), "r"(b1));
}

// split fp32 -> (hi, lo) bf16 pair, packed two-at-a-time into b32 regs
static __device__ __forceinline__ void split_pack2(float a, float b,
                                                   uint32_t& hi, uint32_t& lo) {
    __nv_bfloat16 ha = __float2bfloat16_rn(a);
    __nv_bfloat16 hb = __float2bfloat16_rn(b);
    __nv_bfloat16 la = __float2bfloat16_rn(a - __bfloat162float(ha));
    __nv_bfloat16 lb = __float2bfloat16_rn(b - __bfloat162float(hb));
    __nv_bfloat162 H; H.x = ha; H.y = hb;
    __nv_bfloat162 L; L.x = la; L.y = lb;
    hi = reinterpret_cast<uint32_t&>(H);
    lo = reinterpret_cast<uint32_t&>(L);
}

// split 4 contiguous floats, store hi/lo as one 64-bit store each
static __device__ __forceinline__ void split_store4(float4 v,
                                                    __nv_bfloat16* hrow,
                                                    __nv_bfloat16* lrow) {
    uint32_t h0, l0, h1, l1;
    split_pack2(v.x, v.y, h0, l0);
    split_pack2(v.z, v.w, h1, l1);
    uint2 H = make_uint2(h0, h1);
    uint2 L = make_uint2(l0, l1);
    *reinterpret_cast<uint2*>(hrow) = H;
    *reinterpret_cast<uint2*>(lrow) = L;
}

// ---------------------------------------------------------------------------
// C[M,N] = A[M,K] @ B[N,K]^T (+bias), bf16 3-term split via mma.sync.
// 128x128 block, BK=16, 128 threads = 4 warps in 2(m) x 2(n), warp tile 64x64.
// 24 KB smem -> 2 CTAs/SM; inter-CTA overlap hides global-load latency.
// ---------------------------------------------------------------------------
#define GBK  16
#define APAD 24   // row stride pad: conflict-free ldmatrix

__global__ __launch_bounds__(128, 2) void gemm_nt_mma(const float* __restrict__ A,
                                                      const float* __restrict__ B,
                                                      const float* __restrict__ bias,
                                                      float* __restrict__ C,
                                                      int M, int N, int K)
{
    __shared__ __nv_bfloat16 Ah[128][APAD], Al[128][APAD];
    __shared__ __nv_bfloat16 Bh[128][APAD], Bl[128][APAD];

    const int t    = threadIdx.x;
    const int lane = t & 31;
    const int warp = t >> 5;
    const int wm   = warp >> 1;   // 0..1
    const int wn   = warp & 1;    // 0..1
    const int m0   = blockIdx.y * 128;
    const int n0   = blockIdx.x * 128;

    float acc[4][8][4];
#pragma unroll
    for (int i = 0; i < 4; i++)
#pragma unroll
        for (int j = 0; j < 8; j++)
#pragma unroll
            for (int r = 0; r < 4; r++) acc[i][j][r] = 0.f;

    const int lr = t;             // 0..127 : tile row loaded by this thread
    const float* Ap = A + (size_t)(m0 + lr) * K;
    const float* Bp = B + (size_t)(n0 + lr) * K;

    // precomputed ldmatrix smem offsets
    const int a_row = (lane & 15);
    const int a_col = (lane >> 4) * 8;
    const int b_row = (lane >> 4) * 8 + (lane & 7);
    const int b_col = ((lane >> 3) & 1) * 8;

    for (int k0 = 0; k0 < K; k0 += GBK) {
        // each thread loads one full 16-wide row slice of A and B
        float4 av[2], bv[2];
#pragma unroll
        for (int q = 0; q < 2; q++) {
            av[q] = *reinterpret_cast<const float4*>(Ap + k0 + q * 8);
            bv[q] = *reinterpret_cast<const float4*>(Bp + k0 + q * 8);
        }
        float4 av1[2], bv1[2];
#pragma unroll
        for (int q = 0; q < 2; q++) {
            av1[q] = *reinterpret_cast<const float4*>(Ap + k0 + q * 8 + 4);
            bv1[q] = *reinterpret_cast<const float4*>(Bp + k0 + q * 8 + 4);
        }
        __syncthreads();
#pragma unroll
        for (int q = 0; q < 2; q++) {
            split_store4(av[q],  &Ah[lr][q * 8],     &Al[lr][q * 8]);
            split_store4(av1[q], &Ah[lr][q * 8 + 4], &Al[lr][q * 8 + 4]);
            split_store4(bv[q],  &Bh[lr][q * 8],     &Bl[lr][q * 8]);
            split_store4(bv1[q], &Bh[lr][q * 8 + 4], &Bl[lr][q * 8 + 4]);
        }
        __syncthreads();

        // A fragments: 4 x 16-row chunks, hi+lo
        uint32_t ah[4][4], al[4][4];
#pragma unroll
        for (int mi = 0; mi < 4; mi++) {
            const int row = wm * 64 + mi * 16 + a_row;
            ldsm4(ah[mi][0], ah[mi][1], ah[mi][2], ah[mi][3],
                  smem_u32(&Ah[row][a_col]));
            ldsm4(al[mi][0], al[mi][1], al[mi][2], al[mi][3],
                  smem_u32(&Al[row][a_col]));
        }

        // B fragments per 16-col group; 2 ni values each
#pragma unroll
        for (int gn = 0; gn < 4; gn++) {
            uint32_t bh[2][2], bl[2][2];
            const int row = wn * 64 + gn * 16 + b_row;
            ldsm4(bh[0][0], bh[0][1], bh[1][0], bh[1][1],
                  smem_u32(&Bh[row][b_col]));
            ldsm4(bl[0][0], bl[0][1], bl[1][0], bl[1][1],
                  smem_u32(&Bl[row][b_col]));
#pragma unroll
            for (int mi = 0; mi < 4; mi++)
#pragma unroll
                for (int j = 0; j < 2; j++) {
                    const int ni = gn * 2 + j;
                    mma16816(acc[mi][ni], ah[mi][0], ah[mi][1], ah[mi][2], ah[mi][3],
                             bh[j][0], bh[j][1]);
                    mma16816(acc[mi][ni], ah[mi][0], ah[mi][1], ah[mi][2], ah[mi][3],
                             bl[j][0], bl[j][1]);
                    mma16816(acc[mi][ni], al[mi][0], al[mi][1], al[mi][2], al[mi][3],
                             bh[j][0], bh[j][1]);
                }
        }
    }

    const int g  = lane >> 2;
    const int t4 = lane & 3;
    float bcol0[8], bcol1[8];
#pragma unroll
    for (int ni = 0; ni < 8; ni++) {
        const int col = n0 + wn * 64 + ni * 8 + t4 * 2;
        bcol0[ni] = bias ? bias[col]     : 0.f;
        bcol1[ni] = bias ? bias[col + 1] : 0.f;
    }
#pragma unroll
    for (int mi = 0; mi < 4; mi++)
#pragma unroll
        for (int ni = 0; ni < 8; ni++) {
            const int row = m0 + wm * 64 + mi * 16 + g;
            const int col = n0 + wn * 64 + ni * 8 + t4 * 2;
            float2 w0 = make_float2(acc[mi][ni][0] + bcol0[ni], acc[mi][ni][1] + bcol1[ni]);
            float2 w1 = make_float2(acc[mi][ni][2] + bcol0[ni], acc[mi][ni][3] + bcol1[ni]);
            *reinterpret_cast<float2*>(C + (size_t)row * N + col)       = w0;
            *reinterpret_cast<float2*>(C + (size_t)(row + 8) * N + col) = w1;
        }
}

// ---------------------------------------------------------------------------
// Fused flash attention with bf16 3-term mma (round-3 version, no prefetch).
// One block = one (b,h), 64 q rows. 4 warps (16 q rows each), K/V tiles of 32.
// ---------------------------------------------------------------------------
#define QPAD 72   // 144B row stride: conflict-free ldmatrix (incl. trans)

__global__ __launch_bounds__(128) void attn_mma(const float* __restrict__ qkv,
                                                float* __restrict__ out)
{
    __shared__ __nv_bfloat16 Qh[64][QPAD], Ql[64][QPAD];
    __shared__ __nv_bfloat16 Kh[32][QPAD], Kl[32][QPAD];
    __shared__ __nv_bfloat16 Vh[32][QPAD], Vl[32][QPAD];

    const int t    = threadIdx.x;
    const int lane = t & 31;
    const int warp = t >> 5;
    const int bh_  = blockIdx.y;
    const int b    = bh_ >> 4;
    const int h    = bh_ & 15;
    const int n0   = blockIdx.x * 64;

    const float* base = qkv + (size_t)b * SEQ * (3 * EMBED);
    const int qoff = h * HDIM;
    const int koff = EMBED + h * HDIM;
    const int voff = 2 * EMBED + h * HDIM;

    // Load + split Q tile (64 x 64), pre-scaled by 1/sqrt(D) = 1/8
#pragma unroll
    for (int i = 0; i < 8; i++) {
        const int idx = t + i * 128;
        const int r = idx >> 4;
        const int q = (idx & 15) * 4;
        float4 v = *reinterpret_cast<const float4*>(
            base + (size_t)(n0 + r) * (3 * EMBED) + qoff + q);
        v.x *= 0.125f; v.y *= 0.125f; v.z *= 0.125f; v.w *= 0.125f;
        split_store4(v, &Qh[r][q], &Ql[r][q]);
    }

    float m0r = -CUDART_INF_F, m1r = -CUDART_INF_F;
    float l0r = 0.f, l1r = 0.f;
    float o[8][4];
#pragma unroll
    for (int i = 0; i < 8; i++)
#pragma unroll
        for (int j = 0; j < 4; j++) o[i][j] = 0.f;

    const int g  = lane >> 2;

    const int a_row = warp * 16 + (lane & 15);
    const int a_colbase = (lane >> 4) * 8;
    const int b_row = (lane >> 4) * 8 + (lane & 7);
    const int b_colk = ((lane >> 3) & 1) * 8;
    const int v_rowk = ((lane >> 3) & 1) * 8 + (lane & 7);
    const int v_col  = (lane >> 4) * 8;

    for (int c0 = 0; c0 < SEQ; c0 += 32) {
        __syncthreads();
        // load + split K and V tiles (32 x 64 each)
#pragma unroll
        for (int i = 0; i < 4; i++) {
            const int idx = t + i * 128;
            const int r = idx >> 4;
            const int q = (idx & 15) * 4;
            const float* rp = base + (size_t)(c0 + r) * (3 * EMBED);
            float4 kv = *reinterpret_cast<const float4*>(rp + koff + q);
            split_store4(kv, &Kh[r][q], &Kl[r][q]);
            float4 vv = *reinterpret_cast<const float4*>(rp + voff + q);
            split_store4(vv, &Vh[r][q], &Vl[r][q]);
        }
        __syncthreads();

        // ---- S = Q K^T  (16 rows x 32 cols per warp) ----
        float s[4][4];
#pragma unroll
        for (int i = 0; i < 4; i++)
#pragma unroll
            for (int j = 0; j < 4; j++) s[i][j] = 0.f;

#pragma unroll
        for (int ks = 0; ks < 4; ks++) {
            uint32_t qh[4], ql[4], kh[4][2], kl[4][2];
            const int acol = ks * 16 + a_colbase;
            ldsm4(qh[0], qh[1], qh[2], qh[3], smem_u32(&Qh[a_row][acol]));
            ldsm4(ql[0], ql[1], ql[2], ql[3], smem_u32(&Ql[a_row][acol]));
            const int kcol = ks * 16 + b_colk;
#pragma unroll
            for (int gn = 0; gn < 2; gn++) {
                const int row = gn * 16 + b_row;
                ldsm4(kh[2 * gn][0], kh[2 * gn][1], kh[2 * gn + 1][0], kh[2 * gn + 1][1],
                      smem_u32(&Kh[row][kcol]));
                ldsm4(kl[2 * gn][0], kl[2 * gn][1], kl[2 * gn + 1][0], kl[2 * gn + 1][1],
                      smem_u32(&Kl[row][kcol]));
            }
#pragma unroll
            for (int ni = 0; ni < 4; ni++) {
                mma16816(s[ni], qh[0], qh[1], qh[2], qh[3], kh[ni][0], kh[ni][1]);
                mma16816(s[ni], qh[0], qh[1], qh[2], qh[3], kl[ni][0], kl[ni][1]);
                mma16816(s[ni], ql[0], ql[1], ql[2], ql[3], kh[ni][0], kh[ni][1]);
            }
        }

        // ---- online softmax (rows g and g+8 of this warp's 16) ----
        float mx0 = s[0][0], mx1 = s[0][2];
#pragma unroll
        for (int ni = 0; ni < 4; ni++) {
            mx0 = fmaxf(mx0, fmaxf(s[ni][0], s[ni][1]));
            mx1 = fmaxf(mx1, fmaxf(s[ni][2], s[ni][3]));
        }
        mx0 = fmaxf(mx0, __shfl_xor_sync(0xffffffffu, mx0, 1));
        mx0 = fmaxf(mx0, __shfl_xor_sync(0xffffffffu, mx0, 2));
        mx1 = fmaxf(mx1, __shfl_xor_sync(0xffffffffu, mx1, 1));
        mx1 = fmaxf(mx1, __shfl_xor_sync(0xffffffffu, mx1, 2));

        const float mn0 = fmaxf(m0r, mx0);
        const float mn1 = fmaxf(m1r, mx1);
        const float cor0 = __expf(m0r - mn0);
        const float cor1 = __expf(m1r - mn1);
        float sum0 = 0.f, sum1 = 0.f;
#pragma unroll
        for (int ni = 0; ni < 4; ni++) {
            s[ni][0] = __expf(s[ni][0] - mn0); sum0 += s[ni][0];
            s[ni][1] = __expf(s[ni][1] - mn0); sum0 += s[ni][1];
            s[ni][2] = __expf(s[ni][2] - mn1); sum1 += s[ni][2];
            s[ni][3] = __expf(s[ni][3] - mn1); sum1 += s[ni][3];
        }
        sum0 += __shfl_xor_sync(0xffffffffu, sum0, 1);
        sum0 += __shfl_xor_sync(0xffffffffu, sum0, 2);
        sum1 += __shfl_xor_sync(0xffffffffu, sum1, 1);
        sum1 += __shfl_xor_sync(0xffffffffu, sum1, 2);
        m0r = mn0; m1r = mn1;
        l0r = l0r * cor0 + sum0;
        l1r = l1r * cor1 + sum1;
#pragma unroll
        for (int ni = 0; ni < 8; ni++) {
            o[ni][0] *= cor0; o[ni][1] *= cor0;
            o[ni][2] *= cor1; o[ni][3] *= cor1;
        }

        // ---- pack P (hi/lo) as mma A operands ----
        uint32_t pah[2][4], pal[2][4];
#pragma unroll
        for (int ks2 = 0; ks2 < 2; ks2++) {
            const int f0 = 2 * ks2, f1 = 2 * ks2 + 1;
            split_pack2(s[f0][0], s[f0][1], pah[ks2][0], pal[ks2][0]);
            split_pack2(s[f0][2], s[f0][3], pah[ks2][1], pal[ks2][1]);
            split_pack2(s[f1][0], s[f1][1], pah[ks2][2], pal[ks2][2]);
            split_pack2(s[f1][2], s[f1][3], pah[ks2][3], pal[ks2][3]);
        }

        // ---- O += P V ----
#pragma unroll
        for (int ks2 = 0; ks2 < 2; ks2++) {
            uint32_t vh[8][2], vl[8][2];
            const int rr = ks2 * 16 + v_rowk;
#pragma unroll
            for (int gn = 0; gn < 4; gn++) {
                const int cc = gn * 16 + v_col;
                ldsm4t(vh[2 * gn][0], vh[2 * gn][1], vh[2 * gn + 1][0], vh[2 * gn + 1][1],
                       smem_u32(&Vh[rr][cc]));
                ldsm4t(vl[2 * gn][0], vl[2 * gn][1], vl[2 * gn + 1][0], vl[2 * gn + 1][1],
                       smem_u32(&Vl[rr][cc]));
            }
#pragma unroll
            for (int ni = 0; ni < 8; ni++) {
                mma16816(o[ni], pah[ks2][0], pah[ks2][1], pah[ks2][2], pah[ks2][3],
                         vh[ni][0], vh[ni][1]);
                mma16816(o[ni], pah[ks2][0], pah[ks2][1], pah[ks2][2], pah[ks2][3],
                         vl[ni][0], vl[ni][1]);
                mma16816(o[ni], pal[ks2][0], pal[ks2][1], pal[ks2][2], pal[ks2][3],
                         vh[ni][0], vh[ni][1]);
            }
        }
    }

    // ---- normalize + write [B, N, E] ----
    const float inv0 = 1.f / l0r;
    const float inv1 = 1.f / l1r;
    float* ob = out + (size_t)b * SEQ * EMBED;
    const int row = n0 + warp * 16 + g;
    const int colb = h * HDIM + (lane & 3) * 2;
#pragma unroll
    for (int ni = 0; ni < 8; ni++) {
        const int col = colb + ni * 8;
        float2 w0 = make_float2(o[ni][0] * inv0, o[ni][1] * inv0);
        float2 w1 = make_float2(o[ni][2] * inv1, o[ni][3] * inv1);
        *reinterpret_cast<float2*>(ob + (size_t)row * EMBED + col)       = w0;
        *reinterpret_cast<float2*>(ob + (size_t)(row + 8) * EMBED + col) = w1;
    }
}

// ---------------------------------------------------------------------------
extern "C" void kernel_launch(void* const* d_in, const int* in_sizes, int n_in,
                              void* d_out, int out_size)
{
    const float* x      = (const float*)d_in[0];
    const float* w_qkv  = (const float*)d_in[1];
    const float* w_proj = (const float*)d_in[2];
    const float* b_proj = (const float*)d_in[3];
    float* out = (float*)d_out;

    float* qkv_ptr = nullptr;
    float* attn_ptr = nullptr;
    cudaGetSymbolAddress((void**)&qkv_ptr, g_qkv);
    cudaGetSymbolAddress((void**)&attn_ptr, g_attn);

    // 1) qkv = x @ w_qkv^T : [4096,1024] x [3072,1024]^T
    gemm_nt_mma<<<dim3(3 * EMBED / 128, MROWS / 128), 128>>>(
        x, w_qkv, nullptr, qkv_ptr, MROWS, 3 * EMBED, EMBED);

    // 2) fused attention -> g_attn [4096,1024]
    attn_mma<<<dim3(SEQ / 64, BATCH * HEADS), 128>>>(qkv_ptr, attn_ptr);

    // 3) out = attn @ w_proj^T + b
    gemm_nt_mma<<<dim3(EMBED / 128, MROWS / 128), 128>>>(
        attn_ptr, w_proj, b_proj, out, MROWS, EMBED, EMBED);
}

// round 6
// speedup vs baseline: 1.2106x; 1.2106x over previous
#include <cuda_runtime.h>
#include <cuda_bf16.h>
#include <math_constants.h>
#include <cstdint>

#define BATCH 2
#define SEQ   2048
#define EMBED 1024
#define HEADS 16
#define HDIM  64
#define MROWS (BATCH * SEQ)   // 4096

// ---------------------------------------------------------------------------
// Persistent scratch (__device__ globals; alloc-free rule)
// ---------------------------------------------------------------------------
__device__ __nv_bfloat16 g_x_h[(size_t)MROWS * EMBED];
__device__ __nv_bfloat16 g_x_l[(size_t)MROWS * EMBED];
__device__ __nv_bfloat16 g_wqkv_h[(size_t)3 * EMBED * EMBED];
__device__ __nv_bfloat16 g_wqkv_l[(size_t)3 * EMBED * EMBED];
__device__ __nv_bfloat16 g_wproj_h[(size_t)EMBED * EMBED];
__device__ __nv_bfloat16 g_wproj_l[(size_t)EMBED * EMBED];
__device__ __nv_bfloat16 g_qkv_h[(size_t)MROWS * 3 * EMBED];
__device__ __nv_bfloat16 g_qkv_l[(size_t)MROWS * 3 * EMBED];
__device__ __nv_bfloat16 g_attn_h[(size_t)MROWS * EMBED];
__device__ __nv_bfloat16 g_attn_l[(size_t)MROWS * EMBED];

// ---------------------------------------------------------------------------
// helpers
// ---------------------------------------------------------------------------
static __device__ __forceinline__ uint32_t smem_u32(const void* p) {
    return (uint32_t)__cvta_generic_to_shared(p);
}

static __device__ __forceinline__ void cpasync16(uint32_t dst, const void* src) {
    asm volatile("cp.async.cg.shared.global [%0], [%1], 16;\n"
                 :: "r"(dst), "l"(__cvta_generic_to_global(src)));
}
#define CP_COMMIT() asm volatile("cp.async.commit_group;\n" ::: "memory")
#define CP_WAIT0()  asm volatile("cp.async.wait_group 0;\n" ::: "memory")

static __device__ __forceinline__ void ldsm4(uint32_t& r0, uint32_t& r1,
                                             uint32_t& r2, uint32_t& r3,
                                             uint32_t addr) {
    asm volatile("ldmatrix.sync.aligned.m8n8.x4.shared.b16 {%0,%1,%2,%3},[%4];\n"
                 : "=r"(r0), "=r"(r1), "=r"(r2), "=r"(r3) : "r"(addr));
}

static __device__ __forceinline__ void ldsm4t(uint32_t& r0, uint32_t& r1,
                                              uint32_t& r2, uint32_t& r3,
                                              uint32_t addr) {
    asm volatile("ldmatrix.sync.aligned.m8n8.x4.trans.shared.b16 {%0,%1,%2,%3},[%4];\n"
                 : "=r"(r0), "=r"(r1), "=r"(r2), "=r"(r3) : "r"(addr));
}

static __device__ __forceinline__ void mma16816(float c[4],
                                                uint32_t a0, uint32_t a1,
                                                uint32_t a2, uint32_t a3,
                                                uint32_t b0, uint32_t b1) {
    asm volatile(
        "mma.sync.aligned.m16n8k16.row.col.f32.bf16.bf16.f32 "
        "{%0,%1,%2,%3},{%4,%5,%6,%7},{%8,%9},{%0,%1,%2,%3};\n"
        : "+f"(c[0]), "+f"(c[1]), "+f"(c[2]), "+f"(c[3])
        : "r"(a0), "r"(a1), "r"(a2), "r"(a3), "r"(b0), "r"(b1));
}

// split fp32 -> (hi, lo) bf16 pair, packed two-at-a-time into b32 regs
static __device__ __forceinline__ void split_pack2(float a, float b,
                                                   uint32_t& hi, uint32_t& lo) {
    __nv_bfloat16 ha = __float2bfloat16_rn(a);
    __nv_bfloat16 hb = __float2bfloat16_rn(b);
    __nv_bfloat16 la = __float2bfloat16_rn(a - __bfloat162float(ha));
    __nv_bfloat16 lb = __float2bfloat16_rn(b - __bfloat162float(hb));
    __nv_bfloat162 H; H.x = ha; H.y = hb;
    __nv_bfloat162 L; L.x = la; L.y = lb;
    hi = reinterpret_cast<uint32_t&>(H);
    lo = reinterpret_cast<uint32_t&>(L);
}

// ---------------------------------------------------------------------------
// elementwise fp32 -> bf16 hi/lo split
// ---------------------------------------------------------------------------
__global__ __launch_bounds__(256) void split_kernel(const float* __restrict__ src,
                                                    __nv_bfloat16* __restrict__ h,
                                                    __nv_bfloat16* __restrict__ l,
                                                    int n)
{
    const int i = (blockIdx.x * 256 + threadIdx.x) * 4;
    if (i < n) {
        float4 v = *reinterpret_cast<const float4*>(src + i);
        uint32_t h0, l0, h1, l1;
        split_pack2(v.x, v.y, h0, l0);
        split_pack2(v.z, v.w, h1, l1);
        *reinterpret_cast<uint2*>(h + i) = make_uint2(h0, h1);
        *reinterpret_cast<uint2*>(l + i) = make_uint2(l0, l1);
    }
}

// ---------------------------------------------------------------------------
// C[M,N] = A[M,K] @ B[N,K]^T, A/B pre-split bf16 (hi,lo), 3-term mma.
// 128x128 block, BK=16, 256 threads = 8 warps (2m x 4n, warp tile 64x32).
// cp.async.cg 2-stage pipeline; 48 KB smem; 2 CTAs/SM.
// SPLIT_OUT: write bf16 hi/lo outputs (no bias); else f32 + bias.
// ---------------------------------------------------------------------------
#define GBK  16
#define APAD 24   // 48B row stride: conflict-free ldmatrix

template<bool SPLIT_OUT>
__global__ __launch_bounds__(256, 2) void gemm_bf16p(
    const __nv_bfloat16* __restrict__ Ahg, const __nv_bfloat16* __restrict__ Alg,
    const __nv_bfloat16* __restrict__ Bhg, const __nv_bfloat16* __restrict__ Blg,
    const float* __restrict__ bias,
    float* __restrict__ C,
    __nv_bfloat16* __restrict__ Ch, __nv_bfloat16* __restrict__ Cl,
    int M, int N, int K)
{
    __shared__ __nv_bfloat16 sA[2][2][128][APAD];   // [stage][hi/lo]
    __shared__ __nv_bfloat16 sB[2][2][128][APAD];

    const int t    = threadIdx.x;
    const int lane = t & 31;
    const int warp = t >> 5;
    const int wm   = warp >> 2;   // 0..1
    const int wn   = warp & 3;    // 0..3
    const int m0   = blockIdx.y * 128;
    const int n0   = blockIdx.x * 128;

    float acc[4][4][4];
#pragma unroll
    for (int i = 0; i < 4; i++)
#pragma unroll
        for (int j = 0; j < 4; j++)
#pragma unroll
            for (int r = 0; r < 4; r++) acc[i][j][r] = 0.f;

    // cp.async mapping: 2 threads per 16-wide row slice (16B each)
    const int lrow = t >> 1;            // 0..127
    const int lco  = (t & 1) * 8;       // element offset 0 or 8

    const __nv_bfloat16* Ah_p = Ahg + (size_t)(m0 + lrow) * K + lco;
    const __nv_bfloat16* Al_p = Alg + (size_t)(m0 + lrow) * K + lco;
    const __nv_bfloat16* Bh_p = Bhg + (size_t)(n0 + lrow) * K + lco;
    const __nv_bfloat16* Bl_p = Blg + (size_t)(n0 + lrow) * K + lco;

    // ldmatrix smem offsets
    const int a_row = (lane & 15);
    const int a_col = (lane >> 4) * 8;
    const int b_row = (lane >> 4) * 8 + (lane & 7);
    const int b_col = ((lane >> 3) & 1) * 8;

    const int KT = K / GBK;

    // prologue: stage 0
    cpasync16(smem_u32(&sA[0][0][lrow][lco]), Ah_p);
    cpasync16(smem_u32(&sA[0][1][lrow][lco]), Al_p);
    cpasync16(smem_u32(&sB[0][0][lrow][lco]), Bh_p);
    cpasync16(smem_u32(&sB[0][1][lrow][lco]), Bl_p);
    CP_COMMIT();

    for (int kt = 0; kt < KT; kt++) {
        CP_WAIT0();
        __syncthreads();

        if (kt + 1 < KT) {
            const int st = (kt + 1) & 1;
            const int k0 = (kt + 1) * GBK;
            cpasync16(smem_u32(&sA[st][0][lrow][lco]), Ah_p + k0);
            cpasync16(smem_u32(&sA[st][1][lrow][lco]), Al_p + k0);
            cpasync16(smem_u32(&sB[st][0][lrow][lco]), Bh_p + k0);
            cpasync16(smem_u32(&sB[st][1][lrow][lco]), Bl_p + k0);
            CP_COMMIT();
        }

        const int st = kt & 1;
        uint32_t ah[4][4], al[4][4], bh[4][2], bl[4][2];
#pragma unroll
        for (int mi = 0; mi < 4; mi++) {
            const int row = wm * 64 + mi * 16 + a_row;
            ldsm4(ah[mi][0], ah[mi][1], ah[mi][2], ah[mi][3],
                  smem_u32(&sA[st][0][row][a_col]));
            ldsm4(al[mi][0], al[mi][1], al[mi][2], al[mi][3],
                  smem_u32(&sA[st][1][row][a_col]));
        }
#pragma unroll
        for (int gn = 0; gn < 2; gn++) {
            const int row = wn * 32 + gn * 16 + b_row;
            ldsm4(bh[2 * gn][0], bh[2 * gn][1], bh[2 * gn + 1][0], bh[2 * gn + 1][1],
                  smem_u32(&sB[st][0][row][b_col]));
            ldsm4(bl[2 * gn][0], bl[2 * gn][1], bl[2 * gn + 1][0], bl[2 * gn + 1][1],
                  smem_u32(&sB[st][1][row][b_col]));
        }
#pragma unroll
        for (int mi = 0; mi < 4; mi++)
#pragma unroll
            for (int ni = 0; ni < 4; ni++) {
                mma16816(acc[mi][ni], ah[mi][0], ah[mi][1], ah[mi][2], ah[mi][3],
                         bh[ni][0], bh[ni][1]);
                mma16816(acc[mi][ni], ah[mi][0], ah[mi][1], ah[mi][2], ah[mi][3],
                         bl[ni][0], bl[ni][1]);
                mma16816(acc[mi][ni], al[mi][0], al[mi][1], al[mi][2], al[mi][3],
                         bh[ni][0], bh[ni][1]);
            }
    }

    const int g  = lane >> 2;
    const int t4 = lane & 3;

    if (SPLIT_OUT) {
#pragma unroll
        for (int mi = 0; mi < 4; mi++)
#pragma unroll
            for (int ni = 0; ni < 4; ni++) {
                const int row = m0 + wm * 64 + mi * 16 + g;
                const int col = n0 + wn * 32 + ni * 8 + t4 * 2;
                uint32_t h0, l0, h1, l1;
                split_pack2(acc[mi][ni][0], acc[mi][ni][1], h0, l0);
                split_pack2(acc[mi][ni][2], acc[mi][ni][3], h1, l1);
                *reinterpret_cast<uint32_t*>(Ch + (size_t)row * N + col)       = h0;
                *reinterpret_cast<uint32_t*>(Cl + (size_t)row * N + col)       = l0;
                *reinterpret_cast<uint32_t*>(Ch + (size_t)(row + 8) * N + col) = h1;
                *reinterpret_cast<uint32_t*>(Cl + (size_t)(row + 8) * N + col) = l1;
            }
    } else {
        float bcol0[4], bcol1[4];
#pragma unroll
        for (int ni = 0; ni < 4; ni++) {
            const int col = n0 + wn * 32 + ni * 8 + t4 * 2;
            bcol0[ni] = bias ? bias[col]     : 0.f;
            bcol1[ni] = bias ? bias[col + 1] : 0.f;
        }
#pragma unroll
        for (int mi = 0; mi < 4; mi++)
#pragma unroll
            for (int ni = 0; ni < 4; ni++) {
                const int row = m0 + wm * 64 + mi * 16 + g;
                const int col = n0 + wn * 32 + ni * 8 + t4 * 2;
                float2 w0 = make_float2(acc[mi][ni][0] + bcol0[ni], acc[mi][ni][1] + bcol1[ni]);
                float2 w1 = make_float2(acc[mi][ni][2] + bcol0[ni], acc[mi][ni][3] + bcol1[ni]);
                *reinterpret_cast<float2*>(C + (size_t)row * N + col)       = w0;
                *reinterpret_cast<float2*>(C + (size_t)(row + 8) * N + col) = w1;
            }
    }
}

// ---------------------------------------------------------------------------
// Fused flash attention on pre-split bf16 qkv. One block = (b,h) x 64 q rows.
// 4 warps, K/V tiles of 32, cp.async 2-stage, SW128-swizzled 128B rows.
// Softmax scale 1/8 folded into the exp argument.
// ---------------------------------------------------------------------------
static __device__ __forceinline__ uint32_t sw128(uint32_t base, int row, int colByte) {
    return base + row * 128 + (colByte ^ ((row & 7) << 4));
}

__global__ __launch_bounds__(128) void attn_bf16p(
    const __nv_bfloat16* __restrict__ qh, const __nv_bfloat16* __restrict__ ql,
    __nv_bfloat16* __restrict__ oh, __nv_bfloat16* __restrict__ ol)
{
    __shared__ __nv_bfloat16 sQ[2][64][64];        // [hi/lo], swizzled 128B rows
    __shared__ __nv_bfloat16 sK[2][2][32][64];     // [stage][hi/lo]
    __shared__ __nv_bfloat16 sV[2][2][32][64];

    const int t    = threadIdx.x;
    const int lane = t & 31;
    const int warp = t >> 5;
    const int bh_  = blockIdx.y;
    const int b    = bh_ >> 4;
    const int h    = bh_ & 15;
    const int n0   = blockIdx.x * 64;

    const size_t rowstride = 3 * EMBED;
    const __nv_bfloat16* qh_b = qh + (size_t)b * SEQ * rowstride;
    const __nv_bfloat16* ql_b = ql + (size_t)b * SEQ * rowstride;
    const int qoff = h * HDIM;
    const int koff = EMBED + h * HDIM;
    const int voff = 2 * EMBED + h * HDIM;

    const uint32_t bQ[2] = { smem_u32(&sQ[0][0][0]), smem_u32(&sQ[1][0][0]) };

    // ---- prologue: Q (hi+lo) + K/V stage 0 via cp.async ----
    {
        const int r  = t >> 1;            // 0..63
        const int c4 = (t & 1) * 4;       // 4 chunks of 16B each
#pragma unroll
        for (int c = 0; c < 4; c++) {
            const int ch = c4 + c;
            cpasync16(sw128(bQ[0], r, ch * 16),
                      qh_b + (size_t)(n0 + r) * rowstride + qoff + ch * 8);
            cpasync16(sw128(bQ[1], r, ch * 16),
                      ql_b + (size_t)(n0 + r) * rowstride + qoff + ch * 8);
        }
        const int kr = t >> 2;            // 0..31
        const int c2 = (t & 3) * 2;
#pragma unroll
        for (int c = 0; c < 2; c++) {
            const int ch = c2 + c;
            const size_t go = (size_t)kr * rowstride + ch * 8;
            cpasync16(sw128(smem_u32(&sK[0][0][0][0]), kr, ch * 16), qh_b + go + koff);
            cpasync16(sw128(smem_u32(&sK[0][1][0][0]), kr, ch * 16), ql_b + go + koff);
            cpasync16(sw128(smem_u32(&sV[0][0][0][0]), kr, ch * 16), qh_b + go + voff);
            cpasync16(sw128(smem_u32(&sV[0][1][0][0]), kr, ch * 16), ql_b + go + voff);
        }
        CP_COMMIT();
    }

    float m0r = -CUDART_INF_F, m1r = -CUDART_INF_F;
    float l0r = 0.f, l1r = 0.f;
    float o[8][4];
#pragma unroll
    for (int i = 0; i < 8; i++)
#pragma unroll
        for (int j = 0; j < 4; j++) o[i][j] = 0.f;

    const int g = lane >> 2;
    const float SC = 0.125f;   // 1/sqrt(HDIM)

    const int a_row  = warp * 16 + (lane & 15);
    const int a_cb   = (lane >> 4) * 16;              // byte col within 16-chunk
    const int b_row  = (lane >> 4) * 8 + (lane & 7);
    const int b_cb   = ((lane >> 3) & 1) * 16;
    const int v_rowk = ((lane >> 3) & 1) * 8 + (lane & 7);
    const int v_cb   = (lane >> 4) * 16;

    const int NT = SEQ / 32;
    for (int kt = 0; kt < NT; kt++) {
        CP_WAIT0();
        __syncthreads();

        if (kt + 1 < NT) {
            const int st = (kt + 1) & 1;
            const int c0 = (kt + 1) * 32;
            const int kr = t >> 2;
            const int c2 = (t & 3) * 2;
#pragma unroll
            for (int c = 0; c < 2; c++) {
                const int ch = c2 + c;
                const size_t go = (size_t)(c0 + kr) * rowstride + ch * 8;
                cpasync16(sw128(smem_u32(&sK[st][0][0][0]), kr, ch * 16), qh_b + go + koff);
                cpasync16(sw128(smem_u32(&sK[st][1][0][0]), kr, ch * 16), ql_b + go + koff);
                cpasync16(sw128(smem_u32(&sV[st][0][0][0]), kr, ch * 16), qh_b + go + voff);
                cpasync16(sw128(smem_u32(&sV[st][1][0][0]), kr, ch * 16), ql_b + go + voff);
            }
            CP_COMMIT();
        }

        const int st = kt & 1;
        const uint32_t bK[2] = { smem_u32(&sK[st][0][0][0]), smem_u32(&sK[st][1][0][0]) };
        const uint32_t bV[2] = { smem_u32(&sV[st][0][0][0]), smem_u32(&sV[st][1][0][0]) };

        // ---- S = Q K^T (raw, unscaled) ----
        float s[4][4];
#pragma unroll
        for (int i = 0; i < 4; i++)
#pragma unroll
            for (int j = 0; j < 4; j++) s[i][j] = 0.f;

#pragma unroll
        for (int ks = 0; ks < 4; ks++) {
            uint32_t qhf[4], qlf[4], khf[4][2], klf[4][2];
            ldsm4(qhf[0], qhf[1], qhf[2], qhf[3], sw128(bQ[0], a_row, ks * 32 + a_cb));
            ldsm4(qlf[0], qlf[1], qlf[2], qlf[3], sw128(bQ[1], a_row, ks * 32 + a_cb));
#pragma unroll
            for (int gn = 0; gn < 2; gn++) {
                const int row = gn * 16 + b_row;
                ldsm4(khf[2 * gn][0], khf[2 * gn][1], khf[2 * gn + 1][0], khf[2 * gn + 1][1],
                      sw128(bK[0], row, ks * 32 + b_cb));
                ldsm4(klf[2 * gn][0], klf[2 * gn][1], klf[2 * gn + 1][0], klf[2 * gn + 1][1],
                      sw128(bK[1], row, ks * 32 + b_cb));
            }
#pragma unroll
            for (int ni = 0; ni < 4; ni++) {
                mma16816(s[ni], qhf[0], qhf[1], qhf[2], qhf[3], khf[ni][0], khf[ni][1]);
                mma16816(s[ni], qhf[0], qhf[1], qhf[2], qhf[3], klf[ni][0], klf[ni][1]);
                mma16816(s[ni], qlf[0], qlf[1], qlf[2], qlf[3], khf[ni][0], khf[ni][1]);
            }
        }

        // ---- online softmax (scale folded into exp arg) ----
        float mx0 = s[0][0], mx1 = s[0][2];
#pragma unroll
        for (int ni = 0; ni < 4; ni++) {
            mx0 = fmaxf(mx0, fmaxf(s[ni][0], s[ni][1]));
            mx1 = fmaxf(mx1, fmaxf(s[ni][2], s[ni][3]));
        }
        mx0 = fmaxf(mx0, __shfl_xor_sync(0xffffffffu, mx0, 1));
        mx0 = fmaxf(mx0, __shfl_xor_sync(0xffffffffu, mx0, 2));
        mx1 = fmaxf(mx1, __shfl_xor_sync(0xffffffffu, mx1, 1));
        mx1 = fmaxf(mx1, __shfl_xor_sync(0xffffffffu, mx1, 2));

        const float mn0 = fmaxf(m0r, mx0);
        const float mn1 = fmaxf(m1r, mx1);
        const float cor0 = __expf((m0r - mn0) * SC);
        const float cor1 = __expf((m1r - mn1) * SC);
        float sum0 = 0.f, sum1 = 0.f;
#pragma unroll
        for (int ni = 0; ni < 4; ni++) {
            s[ni][0] = __expf((s[ni][0] - mn0) * SC); sum0 += s[ni][0];
            s[ni][1] = __expf((s[ni][1] - mn0) * SC); sum0 += s[ni][1];
            s[ni][2] = __expf((s[ni][2] - mn1) * SC); sum1 += s[ni][2];
            s[ni][3] = __expf((s[ni][3] - mn1) * SC); sum1 += s[ni][3];
        }
        sum0 += __shfl_xor_sync(0xffffffffu, sum0, 1);
        sum0 += __shfl_xor_sync(0xffffffffu, sum0, 2);
        sum1 += __shfl_xor_sync(0xffffffffu, sum1, 1);
        sum1 += __shfl_xor_sync(0xffffffffu, sum1, 2);
        m0r = mn0; m1r = mn1;
        l0r = l0r * cor0 + sum0;
        l1r = l1r * cor1 + sum1;
#pragma unroll
        for (int ni = 0; ni < 8; ni++) {
            o[ni][0] *= cor0; o[ni][1] *= cor0;
            o[ni][2] *= cor1; o[ni][3] *= cor1;
        }

        // ---- pack P (hi/lo) as mma A operands ----
        uint32_t pah[2][4], pal[2][4];
#pragma unroll
        for (int ks2 = 0; ks2 < 2; ks2++) {
            const int f0 = 2 * ks2, f1 = 2 * ks2 + 1;
            split_pack2(s[f0][0], s[f0][1], pah[ks2][0], pal[ks2][0]);
            split_pack2(s[f0][2], s[f0][3], pah[ks2][1], pal[ks2][1]);
            split_pack2(s[f1][0], s[f1][1], pah[ks2][2], pal[ks2][2]);
            split_pack2(s[f1][2], s[f1][3], pah[ks2][3], pal[ks2][3]);
        }

        // ---- O += P V ----
#pragma unroll
        for (int ks2 = 0; ks2 < 2; ks2++) {
            uint32_t vh[8][2], vl[8][2];
            const int rr = ks2 * 16 + v_rowk;
#pragma unroll
            for (int gn = 0; gn < 4; gn++) {
                ldsm4t(vh[2 * gn][0], vh[2 * gn][1], vh[2 * gn + 1][0], vh[2 * gn + 1][1],
                       sw128(bV[0], rr, gn * 32 + v_cb));
                ldsm4t(vl[2 * gn][0], vl[2 * gn][1], vl[2 * gn + 1][0], vl[2 * gn + 1][1],
                       sw128(bV[1], rr, gn * 32 + v_cb));
            }
#pragma unroll
            for (int ni = 0; ni < 8; ni++) {
                mma16816(o[ni], pah[ks2][0], pah[ks2][1], pah[ks2][2], pah[ks2][3],
                         vh[ni][0], vh[ni][1]);
                mma16816(o[ni], pah[ks2][0], pah[ks2][1], pah[ks2][2], pah[ks2][3],
                         vl[ni][0], vl[ni][1]);
                mma16816(o[ni], pal[ks2][0], pal[ks2][1], pal[ks2][2], pal[ks2][3],
                         vh[ni][0], vh[ni][1]);
            }
        }
    }

    // ---- normalize + split-write to g_attn [B*N, E] ----
    const float inv0 = 1.f / l0r;
    const float inv1 = 1.f / l1r;
    __nv_bfloat16* oh_b = oh + (size_t)b * SEQ * EMBED;
    __nv_bfloat16* ol_b = ol + (size_t)b * SEQ * EMBED;
    const int row  = n0 + warp * 16 + g;
    const int colb = h * HDIM + (lane & 3) * 2;
#pragma unroll
    for (int ni = 0; ni < 8; ni++) {
        const int col = colb + ni * 8;
        uint32_t h0, l0, h1, l1;
        split_pack2(o[ni][0] * inv0, o[ni][1] * inv0, h0, l0);
        split_pack2(o[ni][2] * inv1, o[ni][3] * inv1, h1, l1);
        *reinterpret_cast<uint32_t*>(oh_b + (size_t)row * EMBED + col)       = h0;
        *reinterpret_cast<uint32_t*>(ol_b + (size_t)row * EMBED + col)       = l0;
        *reinterpret_cast<uint32_t*>(oh_b + (size_t)(row + 8) * EMBED + col) = h1;
        *reinterpret_cast<uint32_t*>(ol_b + (size_t)(row + 8) * EMBED + col) = l1;
    }
}

// ---------------------------------------------------------------------------
extern "C" void kernel_launch(void* const* d_in, const int* in_sizes, int n_in,
                              void* d_out, int out_size)
{
    const float* x      = (const float*)d_in[0];
    const float* w_qkv  = (const float*)d_in[1];
    const float* w_proj = (const float*)d_in[2];
    const float* b_proj = (const float*)d_in[3];
    float* out = (float*)d_out;

    __nv_bfloat16 *xh, *xl, *wqh, *wql, *wph, *wpl, *qh, *ql, *ah, *al;
    cudaGetSymbolAddress((void**)&xh,  g_x_h);
    cudaGetSymbolAddress((void**)&xl,  g_x_l);
    cudaGetSymbolAddress((void**)&wqh, g_wqkv_h);
    cudaGetSymbolAddress((void**)&wql, g_wqkv_l);
    cudaGetSymbolAddress((void**)&wph, g_wproj_h);
    cudaGetSymbolAddress((void**)&wpl, g_wproj_l);
    cudaGetSymbolAddress((void**)&qh,  g_qkv_h);
    cudaGetSymbolAddress((void**)&ql,  g_qkv_l);
    cudaGetSymbolAddress((void**)&ah,  g_attn_h);
    cudaGetSymbolAddress((void**)&al,  g_attn_l);

    // 0) split inputs to bf16 hi/lo
    split_kernel<<<(MROWS * EMBED / 4 + 255) / 256, 256>>>(x, xh, xl, MROWS * EMBED);
    split_kernel<<<(3 * EMBED * EMBED / 4 + 255) / 256, 256>>>(w_qkv, wqh, wql, 3 * EMBED * EMBED);
    split_kernel<<<(EMBED * EMBED / 4 + 255) / 256, 256>>>(w_proj, wph, wpl, EMBED * EMBED);

    // 1) qkv = x @ w_qkv^T  (split output)
    gemm_bf16p<true><<<dim3(3 * EMBED / 128, MROWS / 128), 256>>>(
        xh, xl, wqh, wql, nullptr, nullptr, qh, ql, MROWS, 3 * EMBED, EMBED);

    // 2) fused attention -> split g_attn
    attn_bf16p<<<dim3(SEQ / 64, BATCH * HEADS), 128>>>(qh, ql, ah, al);

    // 3) out = attn @ w_proj^T + b  (f32 output)
    gemm_bf16p<false><<<dim3(EMBED / 128, MROWS / 128), 256>>>(
        ah, al, wph, wpl, b_proj, out, nullptr, nullptr, MROWS, EMBED, EMBED);
}